// round 4
// baseline (speedup 1.0000x reference)
#include <cuda_runtime.h>
#include <cstdint>
#include <cfloat>

// VectorQuantization: x (32,64,64,64) fp32, codebook (1024,64) fp32.
// Output: z_q (same shape as x) + scalar vq_loss at the end of d_out.
//
// Numerics contract (DO NOT BREAK — this is what makes rel_err == 0):
//   x_sq : sequential scalar fp32  s = fadd(s, fmul(x,x)), d ascending
//   m    : sequential fused-FMA chain over d ascending of (2x_d)*e_kd
//   d2   : fsub(fadd(x_sq, e_sq), m)   — exactly two roundings
//   ties : lowest code index (jnp.argmin first occurrence)
// fma.rn.f32x2 halves are independent correctly-rounded FMAs == scalar fmaf.

#define N_VEC     131072
#define DIM       64
#define K_CODES   1024
#define HWSZ      4096
#define POS_PER_BLK 128
#define NBLK      (N_VEC / POS_PER_BLK)      // 1024
#define CODES_PER_TILE 64
#define N_TILES   (K_CODES / CODES_PER_TILE) // 16
#define THREADS   256
#define PF_ELEMS  ((CODES_PER_TILE * DIM) / THREADS)   // 16

__device__ float g_esq[K_CODES];
__device__ float g_partial[NBLK];

typedef unsigned long long u64;

__device__ __forceinline__ u64 pack2(float lo, float hi) {
    u64 r;
    asm("mov.b64 %0, {%1, %2};" : "=l"(r) : "r"(__float_as_uint(lo)), "r"(__float_as_uint(hi)));
    return r;
}
__device__ __forceinline__ void unpack2(u64 v, float &lo, float &hi) {
    unsigned int a, b;
    asm("mov.b64 {%0, %1}, %2;" : "=r"(a), "=r"(b) : "l"(v));
    lo = __uint_as_float(a);
    hi = __uint_as_float(b);
}
__device__ __forceinline__ void fma2(u64 &d, u64 a, u64 b) {
    asm("fma.rn.f32x2 %0, %1, %2, %0;" : "+l"(d) : "l"(a), "l"(b));
}

// ---- codebook squared-norms: sequential fp32, separate mul/add roundings ----
__global__ void esq_kernel(const float* __restrict__ cb) {
    int k = blockIdx.x * blockDim.x + threadIdx.x;
    if (k < K_CODES) {
        const float* row = cb + (size_t)k * DIM;
        float s = 0.f;
#pragma unroll
        for (int d = 0; d < DIM; ++d) {
            float v = row[d];
            s = __fadd_rn(s, __fmul_rn(v, v));
        }
        g_esq[k] = s;
    }
}

// ---- main kernel ----
__global__ void __launch_bounds__(THREADS, 2)
vq_main(const float* __restrict__ x, const float* __restrict__ cb, float* __restrict__ out) {
    extern __shared__ float sm[];
    float* x_sT  = sm;                          // [64][128] holds 2*x, d-major (16B aligned)
    u64*   e_dup = (u64*)(x_sT + DIM * POS_PER_BLK);  // [64 d][4 j][16 cg] {ev,ev} = 32KB
    float* esq   = (float*)(e_dup + DIM * CODES_PER_TILE); // [1024]
    float* red   = esq + K_CODES;               // [256]
    float* xsq_s = red + THREADS;               // [128]
    int*   bidx  = (int*)(xsq_s + POS_PER_BLK); // [128]

    const int tid = threadIdx.x;
    const int n0  = blockIdx.x * POS_PER_BLK;
    const int b   = n0 >> 12;
    const int hw0 = n0 & (HWSZ - 1);
    const float* xb = x + (size_t)b * DIM * HWSZ + hw0;

    // x tile scaled by 2 (exact). GMEM is already [d][spatial] -> direct coalesced copy.
#pragma unroll
    for (int it = 0; it < (DIM * POS_PER_BLK) / THREADS; ++it) {
        int e = it * THREADS + tid;
        int d = e >> 7, i = e & 127;
        x_sT[d * POS_PER_BLK + i] = 2.0f * xb[(size_t)d * HWSZ + i];
    }
#pragma unroll
    for (int it = 0; it < K_CODES / THREADS; ++it)
        esq[it * THREADS + tid] = g_esq[it * THREADS + tid];

    // Prefetch tile 0 of the codebook into registers.
    const int pc = tid >> 6;          // code sub-index base contribution
    float pf[PF_ELEMS];
    {
        // element e = it*THREADS + tid -> c = e>>6, d = e&63 (coalesced over d)
#pragma unroll
        for (int it = 0; it < PF_ELEMS; ++it) {
            int e = it * THREADS + tid;
            pf[it] = __ldg(cb + (size_t)((e >> 6)) * DIM + (e & 63));
        }
    }
    __syncthreads();

    // x_sq per position (XLA CPU sequential reduce): term fl(x*x) = fl((2x)^2)*0.25 exact.
    if (tid < POS_PER_BLK) {
        float s = 0.f;
#pragma unroll
        for (int d = 0; d < DIM; ++d) {
            float xv = x_sT[d * POS_PER_BLK + tid];
            float t  = __fmul_rn(__fmul_rn(xv, xv), 0.25f);
            s = __fadd_rn(s, t);
        }
        xsq_s[tid] = s;
    }

    const int pg = tid >> 4;          // 0..15 position group (8 consecutive positions)
    const int cg = tid & 15;          // 0..15 code group (4 codes per tile)
    const int pbase = pg * 8;
    const float* xrow = x_sT + pbase; // thread's 8 positions, 16B aligned
    const u64*  erow  = e_dup + cg;   // stride 16 across j, 64 across d

    float bestS[8];
    int   bestI[8];
#pragma unroll
    for (int p = 0; p < 8; ++p) { bestS[p] = FLT_MAX; bestI[p] = 0; }

    for (int t = 0; t < N_TILES; ++t) {
        // Store prefetched tile into duplicated smem layout [d][j][cg].
        __syncthreads();   // everyone done reading previous tile
#pragma unroll
        for (int it = 0; it < PF_ELEMS; ++it) {
            int e = it * THREADS + tid;
            int c = e >> 6, d = e & 63;
            float v = pf[it];
            e_dup[(d * 4 + (c & 3)) * 16 + (c >> 2)] = pack2(v, v);
        }
        __syncthreads();

        // Issue next tile's global loads now; latency hides under the FMA loop.
        if (t + 1 < N_TILES) {
            const float* cbt = cb + (size_t)(t + 1) * CODES_PER_TILE * DIM;
#pragma unroll
            for (int it = 0; it < PF_ELEMS; ++it) {
                int e = it * THREADS + tid;
                pf[it] = __ldg(cbt + (size_t)(e >> 6) * DIM + (e & 63));
            }
        }

        u64 acc[4][4];
#pragma unroll
        for (int u = 0; u < 4; ++u)
#pragma unroll
            for (int j = 0; j < 4; ++j) acc[u][j] = 0ull;

#pragma unroll 8
        for (int d = 0; d < DIM; ++d) {
            // 8 positions as 2x LDS.128 (broadcast within the 16 cg lanes)
            ulonglong2 xa = *reinterpret_cast<const ulonglong2*>(xrow + d * POS_PER_BLK);
            ulonglong2 xc = *reinterpret_cast<const ulonglong2*>(xrow + d * POS_PER_BLK + 4);
            // 4 code values, pre-duplicated; 16 lanes hit 16 consecutive 8B words
            u64 ep0 = erow[(d * 4 + 0) * 16];
            u64 ep1 = erow[(d * 4 + 1) * 16];
            u64 ep2 = erow[(d * 4 + 2) * 16];
            u64 ep3 = erow[(d * 4 + 3) * 16];

            fma2(acc[0][0], xa.x, ep0); fma2(acc[0][1], xa.x, ep1);
            fma2(acc[0][2], xa.x, ep2); fma2(acc[0][3], xa.x, ep3);
            fma2(acc[1][0], xa.y, ep0); fma2(acc[1][1], xa.y, ep1);
            fma2(acc[1][2], xa.y, ep2); fma2(acc[1][3], xa.y, ep3);
            fma2(acc[2][0], xc.x, ep0); fma2(acc[2][1], xc.x, ep1);
            fma2(acc[2][2], xc.x, ep2); fma2(acc[2][3], xc.x, ep3);
            fma2(acc[3][0], xc.y, ep0); fma2(acc[3][1], xc.y, ep1);
            fma2(acc[3][2], xc.y, ep2); fma2(acc[3][3], xc.y, ep3);
        }

        // d2 = fl( fl(x_sq + e_sq_k) - m_k ) — exactly two roundings as in ref.
#pragma unroll
        for (int j = 0; j < 4; ++j) {
            int c = t * CODES_PER_TILE + cg * 4 + j;
            float eq = esq[c];
#pragma unroll
            for (int u = 0; u < 4; ++u) {
                float lo, hi;
                unpack2(acc[u][j], lo, hi);
                float t0 = __fadd_rn(xsq_s[pbase + 2 * u],     eq);
                float t1 = __fadd_rn(xsq_s[pbase + 2 * u + 1], eq);
                float s0 = __fsub_rn(t0, lo);
                float s1 = __fsub_rn(t1, hi);
                if (s0 < bestS[2 * u])     { bestS[2 * u] = s0;     bestI[2 * u] = c; }
                if (s1 < bestS[2 * u + 1]) { bestS[2 * u + 1] = s1; bestI[2 * u + 1] = c; }
            }
        }
    }

    // Cross-thread argmin over the 16 cg lanes; ties -> smaller index.
#pragma unroll
    for (int p = 0; p < 8; ++p) {
        float s = bestS[p];
        int   i = bestI[p];
#pragma unroll
        for (int o = 8; o >= 1; o >>= 1) {
            float s2 = __shfl_xor_sync(0xFFFFFFFFu, s, o);
            int   i2 = __shfl_xor_sync(0xFFFFFFFFu, i, o);
            if (s2 < s || (s2 == s && i2 < i)) { s = s2; i = i2; }
        }
        if (cg == 0) bidx[pbase + p] = i;
    }
    __syncthreads();

    // Epilogue: gather chosen codes, write z_q (coalesced), accumulate SSE.
    float sse = 0.f;
    float* ob = out + (size_t)b * DIM * HWSZ + hw0;
#pragma unroll
    for (int it = 0; it < (DIM * POS_PER_BLK) / THREADS; ++it) {
        int e = it * THREADS + tid;
        int d = e >> 7, i = e & 127;
        float q  = cb[(size_t)bidx[i] * DIM + d];
        float xv = 0.5f * x_sT[d * POS_PER_BLK + i];
        float df = xv - q;
        sse += df * df;
        ob[(size_t)d * HWSZ + i] = q;
    }
    red[tid] = sse;
    __syncthreads();
#pragma unroll
    for (int o = THREADS / 2; o > 0; o >>= 1) {
        if (tid < o) red[tid] += red[tid + o];
        __syncthreads();
    }
    if (tid == 0) g_partial[blockIdx.x] = red[0];
}

// ---- deterministic loss finalize ----
__global__ void finalize_kernel(float* __restrict__ out, int out_size) {
    __shared__ float red[256];
    int tid = threadIdx.x;
    float s = 0.f;
    for (int i = tid; i < NBLK; i += 256) s += g_partial[i];
    red[tid] = s;
    __syncthreads();
#pragma unroll
    for (int o = 128; o > 0; o >>= 1) {
        if (tid < o) red[tid] += red[tid + o];
        __syncthreads();
    }
    if (tid == 0) {
        float mse = red[0] / (float)(N_VEC * DIM);
        out[out_size - 1] = mse + 0.25f * mse;   // vq_loss = 1.25 * mse
    }
}

extern "C" void kernel_launch(void* const* d_in, const int* in_sizes, int n_in,
                              void* d_out, int out_size) {
    const float* x  = (const float*)d_in[0];
    const float* cb = (const float*)d_in[1];
    float* out = (float*)d_out;

    const int smem_bytes = DIM * POS_PER_BLK * 4            // x_sT  32KB
                         + DIM * CODES_PER_TILE * 8         // e_dup 32KB
                         + K_CODES * 4                      // esq    4KB
                         + THREADS * 4                      // red    1KB
                         + POS_PER_BLK * 4                  // xsq  0.5KB
                         + POS_PER_BLK * 4;                 // bidx 0.5KB
    cudaFuncSetAttribute(vq_main, cudaFuncAttributeMaxDynamicSharedMemorySize, smem_bytes);

    esq_kernel<<<K_CODES / THREADS, THREADS>>>(cb);
    vq_main<<<NBLK, THREADS, smem_bytes>>>(x, cb, out);
    finalize_kernel<<<1, 256>>>(out, out_size);
}